// round 9
// baseline (speedup 1.0000x reference)
#include <cuda_runtime.h>

#define FULLMASK 0xffffffffu
typedef unsigned long long u64;

__device__ __forceinline__ u64 ffma2(u64 a, u64 b, u64 c) {
    u64 r;
    asm("fma.rn.f32x2 %0, %1, %2, %3;" : "=l"(r) : "l"(a), "l"(b), "l"(c));
    return r;
}
__device__ __forceinline__ u64 dup2f(float v) {
    u64 r;
    asm("mov.b64 %0, {%1, %1};" : "=l"(r) : "f"(v));
    return r;
}
__device__ __forceinline__ float2 unpk(u64 p) {
    float2 f;
    asm("mov.b64 {%0, %1}, %2;" : "=f"(f.x), "=f"(f.y) : "l"(p));
    return f;
}

// ---- shared layout (float offsets), one 512-thread block, 64 points ----
#define W2_STRIDE 260
#define W1T_STRIDE 20
#define W1R_STRIDE 68
#define HW_STRIDE 68
#define UD_STRIDE 24
#define TS 20
#define TILE 324              // 324*4=1296 bytes (16B aligned), %32==4 stagger

#define W2S_OFF 0             // 16640
#define W1T_OFF 16640         // 1280
#define W1R_OFF 17920         // 1088
#define B1S_OFF 19008         // 64
#define B2S_OFF 19072         // 256
#define HW_OFF  19328         // 64*68 = 4352
#define HTS2_OFF 23680        // 16 warps * 512 floats (= 256 u64 {h,h} per warp)
#define STT_OFF 31872         // 16 warps * 64
#define VTT_OFF 32896         // 16 warps * 64
#define USC_OFF 33920         // 64*24
#define DSC_OFF 35456         // 64*24
#define TILES_OFF 36992       // 64*324 = 20736
#define SMEM_FLOATS 57728
#define SMEM_BYTES (SMEM_FLOATS * 4)   // 230912

// One acceleration evaluation. Warp handles 4 points; lane=(g,sub),
// g=lane>>3 (point), sub=lane&7. All scratch is warp-private.
__device__ __noinline__ float2 geo_dv(float xe0, float xe1, float ve0, float ve1,
                                      int lane, int sub, int g, int warp)
{
    extern __shared__ float smem[];
    const float* W2s = smem + W2S_OFF;
    const float* W1t = smem + W1T_OFF;
    const float* W1r = smem + W1R_OFF;
    const float* b1s = smem + B1S_OFF;
    const float* b2s = smem + B2S_OFF;
    float* hw    = smem + HW_OFF;
    u64*   hts2  = (u64*)(smem + HTS2_OFF) + warp * 256;   // [c*4 + pt] = {h,h}
    float* stT   = smem + STT_OFF + warp * 64;
    float* vtT   = smem + VTT_OFF + warp * 64;
    float* usc   = smem + USC_OFF;
    float* dsc   = smem + DSC_OFF;
    float* tiles = smem + TILES_OFF + warp * 4 * TILE;

    const int gbase = lane & 24;
    const int lp = warp * 4 + g;

    __syncwarp();   // previous eval fully consumed
    vtT[sub * 4 + g] = ve0;
    vtT[(sub + 8) * 4 + g] = ve1;

    // ---- replicate x, v of own point ----
    float x[16], v[16];
#pragma unroll
    for (int a = 0; a < 8; a++) {
        x[a]     = __shfl_sync(FULLMASK, xe0, gbase + a);
        x[a + 8] = __shfl_sync(FULLMASK, xe1, gbase + a);
        v[a]     = __shfl_sync(FULLMASK, ve0, gbase + a);
        v[a + 8] = __shfl_sync(FULLMASK, ve1, gbase + a);
    }

    // ---- hidden layer: lane owns channels c = sub + 8j of its point ----
#pragma unroll
    for (int j = 0; j < 8; j++) {
        const int c = sub + 8 * j;
        float pre = b1s[c];
        const float4* wr = (const float4*)(W1t + c * W1T_STRIDE);
#pragma unroll
        for (int t = 0; t < 4; t++) {
            const float4 w = wr[t];
            pre = fmaf(w.x, x[4 * t + 0], pre);
            pre = fmaf(w.y, x[4 * t + 1], pre);
            pre = fmaf(w.z, x[4 * t + 2], pre);
            pre = fmaf(w.w, x[4 * t + 3], pre);
        }
        hts2[c * 4 + g] = dup2f(tanhf(pre));
    }
    __syncwarp();   // hts2, vtT visible warp-wide

    // ---- A pass: one W2 sweep serves all 4 points, packed col-pairs ----
    // lane owns flat cols [4l,4l+4) (a) and [128+4l,..) (b); each as 2 f32x2.
    u64 a0[4], a1[4], bb0[4], bb1[4];
    {
        const ulonglong2 bza = *(const ulonglong2*)(b2s + 4 * lane);
        const ulonglong2 bzb = *(const ulonglong2*)(b2s + 128 + 4 * lane);
#pragma unroll
        for (int pt = 0; pt < 4; pt++) {
            a0[pt] = bza.x; a1[pt] = bza.y;
            bb0[pt] = bzb.x; bb1[pt] = bzb.y;
        }
    }
#pragma unroll 8
    for (int r = 0; r < 64; r++) {
        const ulonglong2 h01 = *(const ulonglong2*)(hts2 + r * 4);
        const ulonglong2 h23 = *(const ulonglong2*)(hts2 + r * 4 + 2);
        const ulonglong2 wa = *(const ulonglong2*)(W2s + r * W2_STRIDE + 4 * lane);
        const ulonglong2 wb = *(const ulonglong2*)(W2s + r * W2_STRIDE + 128 + 4 * lane);
        a0[0] = ffma2(h01.x, wa.x, a0[0]);  a1[0] = ffma2(h01.x, wa.y, a1[0]);
        bb0[0] = ffma2(h01.x, wb.x, bb0[0]); bb1[0] = ffma2(h01.x, wb.y, bb1[0]);
        a0[1] = ffma2(h01.y, wa.x, a0[1]);  a1[1] = ffma2(h01.y, wa.y, a1[1]);
        bb0[1] = ffma2(h01.y, wb.x, bb0[1]); bb1[1] = ffma2(h01.y, wb.y, bb1[1]);
        a0[2] = ffma2(h23.x, wa.x, a0[2]);  a1[2] = ffma2(h23.x, wa.y, a1[2]);
        bb0[2] = ffma2(h23.x, wb.x, bb0[2]); bb1[2] = ffma2(h23.x, wb.y, bb1[2]);
        a0[3] = ffma2(h23.y, wa.x, a0[3]);  a1[3] = ffma2(h23.y, wa.y, a1[3]);
        bb0[3] = ffma2(h23.y, wb.x, bb0[3]); bb1[3] = ffma2(h23.y, wb.y, bb1[3]);
    }

    // ---- stage A tiles (stores are bit-identical to float4 stores) ----
    __syncwarp();
    {
        const int prow = lane >> 2;
        const int qcol = (lane & 3) * 4;
#pragma unroll
        for (int pt = 0; pt < 4; pt++) {
            *(ulonglong2*)(tiles + pt * TILE + prow * TS + qcol) =
                make_ulonglong2(a0[pt], a1[pt]);
            *(ulonglong2*)(tiles + pt * TILE + (8 + prow) * TS + qcol) =
                make_ulonglong2(bb0[pt], bb1[pt]);
        }
    }
    __syncwarp();

    // ---- s = A^T v (own point), staged transposed ----
    {
        const float* myt = tiles + g * TILE;
        float s0 = 0.0f, s1 = 0.0f;
#pragma unroll
        for (int p = 0; p < 16; p++) {
            s0 = fmaf(myt[p * TS + sub], v[p], s0);
            s1 = fmaf(myt[p * TS + sub + 8], v[p], s1);
        }
        stT[sub * 4 + g] = s0;
        stT[(sub + 8) * 4 + g] = s1;
    }
    __syncwarp();

    // ---- m pass: lane owns W2 rows r0=lane, r1=lane+32 for ALL 4 points ----
    // pt-pair packed accumulators; s, v free-packed from stT/vtT.
    {
        u64 m0a = 0, m0b = 0, m1a = 0, m1b = 0;
        const float* R0 = W2s + lane * W2_STRIDE;
        const float* R1 = W2s + (lane + 32) * W2_STRIDE;
#pragma unroll
        for (int qh = 0; qh < 2; qh++) {
            u64 sqa[8], sqb[8];
#pragma unroll
            for (int q8 = 0; q8 < 8; q8++) {
                const ulonglong2 sv = *(const ulonglong2*)(stT + (qh * 8 + q8) * 4);
                sqa[q8] = sv.x; sqb[q8] = sv.y;
            }
#pragma unroll
            for (int p = 0; p < 16; p++) {
                const ulonglong2 vp2 = *(const ulonglong2*)(vtT + p * 4);
                const float4 wa0 = *(const float4*)(R0 + 16 * p + 8 * qh);
                const float4 wb0 = *(const float4*)(R0 + 16 * p + 8 * qh + 4);
                const float4 wa1 = *(const float4*)(R1 + 16 * p + 8 * qh);
                const float4 wb1 = *(const float4*)(R1 + 16 * p + 8 * qh + 4);
                u64 d0a = 0, d0b = 0, d1a = 0, d1b = 0;
                u64 wd;
                wd = dup2f(wa0.x); d0a = ffma2(wd, sqa[0], d0a); d0b = ffma2(wd, sqb[0], d0b);
                wd = dup2f(wa0.y); d0a = ffma2(wd, sqa[1], d0a); d0b = ffma2(wd, sqb[1], d0b);
                wd = dup2f(wa0.z); d0a = ffma2(wd, sqa[2], d0a); d0b = ffma2(wd, sqb[2], d0b);
                wd = dup2f(wa0.w); d0a = ffma2(wd, sqa[3], d0a); d0b = ffma2(wd, sqb[3], d0b);
                wd = dup2f(wb0.x); d0a = ffma2(wd, sqa[4], d0a); d0b = ffma2(wd, sqb[4], d0b);
                wd = dup2f(wb0.y); d0a = ffma2(wd, sqa[5], d0a); d0b = ffma2(wd, sqb[5], d0b);
                wd = dup2f(wb0.z); d0a = ffma2(wd, sqa[6], d0a); d0b = ffma2(wd, sqb[6], d0b);
                wd = dup2f(wb0.w); d0a = ffma2(wd, sqa[7], d0a); d0b = ffma2(wd, sqb[7], d0b);
                wd = dup2f(wa1.x); d1a = ffma2(wd, sqa[0], d1a); d1b = ffma2(wd, sqb[0], d1b);
                wd = dup2f(wa1.y); d1a = ffma2(wd, sqa[1], d1a); d1b = ffma2(wd, sqb[1], d1b);
                wd = dup2f(wa1.z); d1a = ffma2(wd, sqa[2], d1a); d1b = ffma2(wd, sqb[2], d1b);
                wd = dup2f(wa1.w); d1a = ffma2(wd, sqa[3], d1a); d1b = ffma2(wd, sqb[3], d1b);
                wd = dup2f(wb1.x); d1a = ffma2(wd, sqa[4], d1a); d1b = ffma2(wd, sqb[4], d1b);
                wd = dup2f(wb1.y); d1a = ffma2(wd, sqa[5], d1a); d1b = ffma2(wd, sqb[5], d1b);
                wd = dup2f(wb1.z); d1a = ffma2(wd, sqa[6], d1a); d1b = ffma2(wd, sqb[6], d1b);
                wd = dup2f(wb1.w); d1a = ffma2(wd, sqa[7], d1a); d1b = ffma2(wd, sqb[7], d1b);
                m0a = ffma2(vp2.x, d0a, m0a); m0b = ffma2(vp2.y, d0b, m0b);
                m1a = ffma2(vp2.x, d1a, m1a); m1b = ffma2(vp2.y, d1b, m1b);
            }
        }
        const float2 m001 = unpk(m0a), m023 = unpk(m0b);
        const float2 m101 = unpk(m1a), m123 = unpk(m1b);
        const float m0[4] = {m001.x, m001.y, m023.x, m023.y};
        const float m1[4] = {m101.x, m101.y, m123.x, m123.y};
#pragma unroll
        for (int pt = 0; pt < 4; pt++) {
            const float h0 = unpk(hts2[lane * 4 + pt]).x;
            const float h1 = unpk(hts2[(lane + 32) * 4 + pt]).x;
            const float th0 = fmaf(-h0, h0, 1.0f);
            const float th1 = fmaf(-h1, h1, 1.0f);
            hw[(warp * 4 + pt) * HW_STRIDE + lane] = 2.0f * th0 * m0[pt];
            hw[(warp * 4 + pt) * HW_STRIDE + lane + 32] = 2.0f * th1 * m1[pt];
        }
    }
    __syncwarp();

    // ---- u rows sub, sub+8 of own point (packed) ----
    {
        u64 u0p = 0, u1p = 0;
        const float* wc = hw + lp * HW_STRIDE;
        const float* r0 = W1r + sub * W1R_STRIDE;
        const float* r1 = W1r + (sub + 8) * W1R_STRIDE;
#pragma unroll
        for (int t = 0; t < 16; t++) {
            const ulonglong2 cc = *(const ulonglong2*)(wc + 4 * t);
            const ulonglong2 w0 = *(const ulonglong2*)(r0 + 4 * t);
            const ulonglong2 w1 = *(const ulonglong2*)(r1 + 4 * t);
            u0p = ffma2(w0.x, cc.x, u0p); u0p = ffma2(w0.y, cc.y, u0p);
            u1p = ffma2(w1.x, cc.x, u1p); u1p = ffma2(w1.y, cc.y, u1p);
        }
        const float2 f0 = unpk(u0p);
        const float2 f1 = unpk(u1p);
        usc[lp * UD_STRIDE + sub] = f0.x + f0.y;
        usc[lp * UD_STRIDE + sub + 8] = f1.x + f1.y;
    }
    __syncwarp();

    // ---- g-build (packed) + interleaved dual SPD solve ----
    const int half = lane >> 4;
    const int i16 = lane & 15;
    {
        const float* TA = tiles + half * TILE;
        const float* TB = tiles + (2 + half) * TILE;

        float growA[16], growB[16];
        {
            u64 ar2[8];
#pragma unroll
            for (int t = 0; t < 4; t++) {
                const ulonglong2 w = *(const ulonglong2*)(TA + i16 * TS + 4 * t);
                ar2[2 * t] = w.x; ar2[2 * t + 1] = w.y;
            }
#pragma unroll
            for (int jr = 0; jr < 16; jr++) {
                u64 gp = 0;
#pragma unroll
                for (int t = 0; t < 4; t++) {
                    const ulonglong2 w = *(const ulonglong2*)(TA + jr * TS + 4 * t);
                    gp = ffma2(ar2[2 * t], w.x, gp);
                    gp = ffma2(ar2[2 * t + 1], w.y, gp);
                }
                const float2 gf = unpk(gp);
                growA[jr] = gf.x + gf.y + ((jr == i16) ? 1.0f : 0.0f);
            }
#pragma unroll
            for (int t = 0; t < 4; t++) {
                const ulonglong2 w = *(const ulonglong2*)(TB + i16 * TS + 4 * t);
                ar2[2 * t] = w.x; ar2[2 * t + 1] = w.y;
            }
#pragma unroll
            for (int jr = 0; jr < 16; jr++) {
                u64 gp = 0;
#pragma unroll
                for (int t = 0; t < 4; t++) {
                    const ulonglong2 w = *(const ulonglong2*)(TB + jr * TS + 4 * t);
                    gp = ffma2(ar2[2 * t], w.x, gp);
                    gp = ffma2(ar2[2 * t + 1], w.y, gp);
                }
                const float2 gf = unpk(gp);
                growB[jr] = gf.x + gf.y + ((jr == i16) ? 1.0f : 0.0f);
            }
        }
        float rhsA = usc[(warp * 4 + half) * UD_STRIDE + i16];
        float rhsB = usc[(warp * 4 + 2 + half) * UD_STRIDE + i16];

#pragma unroll
        for (int k = 0; k < 15; k++) {
            const float pivA = __shfl_sync(FULLMASK, growA[k], k, 16);
            const float pivB = __shfl_sync(FULLMASK, growB[k], k, 16);
            const float prA = __shfl_sync(FULLMASK, rhsA, k, 16);
            const float prB = __shfl_sync(FULLMASK, rhsB, k, 16);
            const float facA = growA[k] * __fdividef(1.0f, pivA);
            const float facB = growB[k] * __fdividef(1.0f, pivB);
            const bool act = (i16 > k);
#pragma unroll
            for (int q = k + 1; q < 16; q++) {
                const float pqA = __shfl_sync(FULLMASK, growA[q], k, 16);
                const float pqB = __shfl_sync(FULLMASK, growB[q], k, 16);
                if (act) {
                    growA[q] = fmaf(-facA, pqA, growA[q]);
                    growB[q] = fmaf(-facB, pqB, growB[q]);
                }
            }
            if (act) {
                rhsA = fmaf(-facA, prA, rhsA);
                rhsB = fmaf(-facB, prB, rhsB);
            }
        }
        float dvlA = 0.0f, dvlB = 0.0f;
#pragma unroll
        for (int k = 15; k >= 0; k--) {
            const float numA = __shfl_sync(FULLMASK, rhsA, k, 16);
            const float numB = __shfl_sync(FULLMASK, rhsB, k, 16);
            const float denA = __shfl_sync(FULLMASK, growA[k], k, 16);
            const float denB = __shfl_sync(FULLMASK, growB[k], k, 16);
            const float ykA = __fdividef(numA, denA);
            const float ykB = __fdividef(numB, denB);
            if (i16 < k) {
                rhsA = fmaf(-growA[k], ykA, rhsA);
                rhsB = fmaf(-growB[k], ykB, rhsB);
            }
            if (i16 == k) { dvlA = -0.5f * ykA; dvlB = -0.5f * ykB; }
        }
        dsc[(warp * 4 + half) * UD_STRIDE + i16] = dvlA;
        dsc[(warp * 4 + 2 + half) * UD_STRIDE + i16] = dvlB;
    }
    __syncwarp();

    float2 res;
    res.x = dsc[lp * UD_STRIDE + sub];
    res.y = dsc[lp * UD_STRIDE + sub + 8];
    return res;
}

__global__ __launch_bounds__(512, 1)
void NeuralGeodesicFlows_45784351375900_kernel(
    const float* __restrict__ z_in,
    const float* __restrict__ t_ptr,
    const float* __restrict__ W1,
    const float* __restrict__ b1,
    const float* __restrict__ W2,
    const float* __restrict__ b2,
    const int* __restrict__ ns_ptr,
    float* __restrict__ z_out,
    int B)
{
    extern __shared__ float smem[];
    const int tid = threadIdx.x;

    for (int idx = tid; idx < 64 * 256; idx += 512)
        smem[W2S_OFF + (idx >> 8) * W2_STRIDE + (idx & 255)] = W2[idx];
    for (int idx = tid; idx < 16 * 64; idx += 512) {
        const int a = idx >> 6, c = idx & 63;
        const float w = W1[idx];
        smem[W1R_OFF + a * W1R_STRIDE + c] = w;
        smem[W1T_OFF + c * W1T_STRIDE + a] = w;
    }
    if (tid < 64) smem[B1S_OFF + tid] = b1[tid];
    if (tid < 256) smem[B2S_OFF + tid] = b2[tid];
    __syncthreads();

    const int warp = tid >> 5;
    const int lane = tid & 31;
    const int sub = lane & 7;
    const int g = lane >> 3;
    const int point = blockIdx.x * 64 + warp * 4 + g;
    if (point >= B) return;

    const float* zp = z_in + point * 32;
    float xs0 = zp[sub];
    float xs1 = zp[sub + 8];
    float vs0 = zp[16 + sub];
    float vs1 = zp[24 + sub];

    const float t = *t_ptr;
    const int ns = *ns_ptr;
    const float dt = t / (float)ns;
    const float hdt = 0.5f * dt;
    const float dt6 = dt * (1.0f / 6.0f);

    for (int s = 0; s < ns; s++) {
        const float2 a1 = geo_dv(xs0, xs1, vs0, vs1, lane, sub, g, warp);
        const float v20 = fmaf(hdt, a1.x, vs0);
        const float v21 = fmaf(hdt, a1.y, vs1);
        const float2 a2 = geo_dv(fmaf(hdt, vs0, xs0), fmaf(hdt, vs1, xs1),
                                 v20, v21, lane, sub, g, warp);
        const float v30 = fmaf(hdt, a2.x, vs0);
        const float v31 = fmaf(hdt, a2.y, vs1);
        const float2 a3 = geo_dv(fmaf(hdt, v20, xs0), fmaf(hdt, v21, xs1),
                                 v30, v31, lane, sub, g, warp);
        const float v40 = fmaf(dt, a3.x, vs0);
        const float v41 = fmaf(dt, a3.y, vs1);
        const float2 a4 = geo_dv(fmaf(dt, v30, xs0), fmaf(dt, v31, xs1),
                                 v40, v41, lane, sub, g, warp);
        xs0 = fmaf(dt6, vs0 + 2.0f * v20 + 2.0f * v30 + v40, xs0);
        xs1 = fmaf(dt6, vs1 + 2.0f * v21 + 2.0f * v31 + v41, xs1);
        vs0 = fmaf(dt6, a1.x + 2.0f * a2.x + 2.0f * a3.x + a4.x, vs0);
        vs1 = fmaf(dt6, a1.y + 2.0f * a2.y + 2.0f * a3.y + a4.y, vs1);
    }

    float* op = z_out + point * 32;
    op[sub] = xs0;
    op[sub + 8] = xs1;
    op[16 + sub] = vs0;
    op[24 + sub] = vs1;
}

extern "C" void kernel_launch(void* const* d_in, const int* in_sizes, int n_in,
                              void* d_out, int out_size)
{
    const float* z  = (const float*)d_in[0];
    const float* t  = (const float*)d_in[1];
    const float* W1 = (const float*)d_in[2];
    const float* b1 = (const float*)d_in[3];
    const float* W2 = (const float*)d_in[4];
    const float* b2 = (const float*)d_in[5];
    const int*   ns = (const int*)d_in[6];
    float* out = (float*)d_out;

    const int B = in_sizes[0] / 32;
    const int grid = (B + 63) / 64;

    cudaFuncSetAttribute(NeuralGeodesicFlows_45784351375900_kernel,
                         cudaFuncAttributeMaxDynamicSharedMemorySize, SMEM_BYTES);
    NeuralGeodesicFlows_45784351375900_kernel<<<grid, 512, SMEM_BYTES>>>(
        z, t, W1, b1, W2, b2, ns, out, B);
}

// round 10
// speedup vs baseline: 1.0007x; 1.0007x over previous
#include <cuda_runtime.h>

#define FULLMASK 0xffffffffu
typedef unsigned long long u64;

__device__ __forceinline__ u64 ffma2(u64 a, u64 b, u64 c) {
    u64 r;
    asm("fma.rn.f32x2 %0, %1, %2, %3;" : "=l"(r) : "l"(a), "l"(b), "l"(c));
    return r;
}
__device__ __forceinline__ u64 dup2f(float v) {
    u64 r;
    asm("mov.b64 %0, {%1, %1};" : "=l"(r) : "f"(v));
    return r;
}
__device__ __forceinline__ float2 unpk(u64 p) {
    float2 f;
    asm("mov.b64 {%0, %1}, %2;" : "=f"(f.x), "=f"(f.y) : "l"(p));
    return f;
}

// ---- shared layout (float offsets), one 512-thread block, 64 points ----
#define W2_STRIDE 260
#define W1T_STRIDE 20
#define W1R_STRIDE 68
#define HW_STRIDE 68
#define UD_STRIDE 24
#define TS 20
#define TILE 324              // 324*4=1296 bytes (16B aligned), %32==4 stagger

#define W2S_OFF 0             // 16640
#define W1T_OFF 16640         // 1280
#define W1R_OFF 17920         // 1088
#define B1S_OFF 19008         // 64
#define B2S_OFF 19072         // 256
#define HW_OFF  19328         // 64*68 = 4352
#define HTS2_OFF 23680        // 16 warps * 512 floats (= 256 u64 {h,h} per warp)
#define STT_OFF 31872         // 16 warps * 64
#define VTT_OFF 32896         // 16 warps * 64
#define USC_OFF 33920         // 64*24
#define DSC_OFF 35456         // 64*24
#define TILES_OFF 36992       // 64*324 = 20736
#define SMEM_FLOATS 57728
#define SMEM_BYTES (SMEM_FLOATS * 4)   // 230912

// One acceleration evaluation. Warp handles 4 points; lane=(g,sub),
// g=lane>>3 (point), sub=lane&7. All scratch is warp-private.
__device__ __noinline__ float2 geo_dv(float xe0, float xe1, float ve0, float ve1,
                                      int lane, int sub, int g, int warp)
{
    extern __shared__ float smem[];
    const float* W2s = smem + W2S_OFF;
    const float* W1t = smem + W1T_OFF;
    const float* W1r = smem + W1R_OFF;
    const float* b1s = smem + B1S_OFF;
    const float* b2s = smem + B2S_OFF;
    float* hw    = smem + HW_OFF;
    u64*   hts2  = (u64*)(smem + HTS2_OFF) + warp * 256;   // [c*4 + pt] = {h,h}
    float* stT   = smem + STT_OFF + warp * 64;
    float* vtT   = smem + VTT_OFF + warp * 64;
    float* usc   = smem + USC_OFF;
    float* dsc   = smem + DSC_OFF;
    float* tiles = smem + TILES_OFF + warp * 4 * TILE;

    const int gbase = lane & 24;
    const int lp = warp * 4 + g;

    __syncwarp();   // previous eval fully consumed
    vtT[sub * 4 + g] = ve0;
    vtT[(sub + 8) * 4 + g] = ve1;

    // ---- replicate x, v of own point ----
    float x[16], v[16];
#pragma unroll
    for (int a = 0; a < 8; a++) {
        x[a]     = __shfl_sync(FULLMASK, xe0, gbase + a);
        x[a + 8] = __shfl_sync(FULLMASK, xe1, gbase + a);
        v[a]     = __shfl_sync(FULLMASK, ve0, gbase + a);
        v[a + 8] = __shfl_sync(FULLMASK, ve1, gbase + a);
    }

    // ---- hidden layer: lane owns channels c = sub + 8j of its point ----
#pragma unroll
    for (int j = 0; j < 8; j++) {
        const int c = sub + 8 * j;
        float pre = b1s[c];
        const float4* wr = (const float4*)(W1t + c * W1T_STRIDE);
#pragma unroll
        for (int t = 0; t < 4; t++) {
            const float4 w = wr[t];
            pre = fmaf(w.x, x[4 * t + 0], pre);
            pre = fmaf(w.y, x[4 * t + 1], pre);
            pre = fmaf(w.z, x[4 * t + 2], pre);
            pre = fmaf(w.w, x[4 * t + 3], pre);
        }
        hts2[c * 4 + g] = dup2f(tanhf(pre));
    }
    __syncwarp();   // hts2, vtT visible warp-wide

    // ---- A pass: one W2 sweep serves all 4 points, packed col-pairs ----
    // lane owns flat cols [4l,4l+4) (a) and [128+4l,..) (b); each as 2 f32x2.
    u64 a0[4], a1[4], bb0[4], bb1[4];
    {
        const ulonglong2 bza = *(const ulonglong2*)(b2s + 4 * lane);
        const ulonglong2 bzb = *(const ulonglong2*)(b2s + 128 + 4 * lane);
#pragma unroll
        for (int pt = 0; pt < 4; pt++) {
            a0[pt] = bza.x; a1[pt] = bza.y;
            bb0[pt] = bzb.x; bb1[pt] = bzb.y;
        }
    }
#pragma unroll 8
    for (int r = 0; r < 64; r++) {
        const ulonglong2 h01 = *(const ulonglong2*)(hts2 + r * 4);
        const ulonglong2 h23 = *(const ulonglong2*)(hts2 + r * 4 + 2);
        const ulonglong2 wa = *(const ulonglong2*)(W2s + r * W2_STRIDE + 4 * lane);
        const ulonglong2 wb = *(const ulonglong2*)(W2s + r * W2_STRIDE + 128 + 4 * lane);
        a0[0] = ffma2(h01.x, wa.x, a0[0]);  a1[0] = ffma2(h01.x, wa.y, a1[0]);
        bb0[0] = ffma2(h01.x, wb.x, bb0[0]); bb1[0] = ffma2(h01.x, wb.y, bb1[0]);
        a0[1] = ffma2(h01.y, wa.x, a0[1]);  a1[1] = ffma2(h01.y, wa.y, a1[1]);
        bb0[1] = ffma2(h01.y, wb.x, bb0[1]); bb1[1] = ffma2(h01.y, wb.y, bb1[1]);
        a0[2] = ffma2(h23.x, wa.x, a0[2]);  a1[2] = ffma2(h23.x, wa.y, a1[2]);
        bb0[2] = ffma2(h23.x, wb.x, bb0[2]); bb1[2] = ffma2(h23.x, wb.y, bb1[2]);
        a0[3] = ffma2(h23.y, wa.x, a0[3]);  a1[3] = ffma2(h23.y, wa.y, a1[3]);
        bb0[3] = ffma2(h23.y, wb.x, bb0[3]); bb1[3] = ffma2(h23.y, wb.y, bb1[3]);
    }

    // ---- stage A tiles (stores are bit-identical to float4 stores) ----
    __syncwarp();
    {
        const int prow = lane >> 2;
        const int qcol = (lane & 3) * 4;
#pragma unroll
        for (int pt = 0; pt < 4; pt++) {
            *(ulonglong2*)(tiles + pt * TILE + prow * TS + qcol) =
                make_ulonglong2(a0[pt], a1[pt]);
            *(ulonglong2*)(tiles + pt * TILE + (8 + prow) * TS + qcol) =
                make_ulonglong2(bb0[pt], bb1[pt]);
        }
    }
    __syncwarp();

    // ---- s = A^T v (own point), staged transposed ----
    {
        const float* myt = tiles + g * TILE;
        float s0 = 0.0f, s1 = 0.0f;
#pragma unroll
        for (int p = 0; p < 16; p++) {
            s0 = fmaf(myt[p * TS + sub], v[p], s0);
            s1 = fmaf(myt[p * TS + sub + 8], v[p], s1);
        }
        stT[sub * 4 + g] = s0;
        stT[(sub + 8) * 4 + g] = s1;
    }
    __syncwarp();

    // ---- m pass: lane owns W2 rows r0=lane, r1=lane+32 for ALL 4 points ----
    // pt-pair packed accumulators; s, v free-packed from stT/vtT.
    {
        u64 m0a = 0, m0b = 0, m1a = 0, m1b = 0;
        const float* R0 = W2s + lane * W2_STRIDE;
        const float* R1 = W2s + (lane + 32) * W2_STRIDE;
#pragma unroll
        for (int qh = 0; qh < 2; qh++) {
            u64 sqa[8], sqb[8];
#pragma unroll
            for (int q8 = 0; q8 < 8; q8++) {
                const ulonglong2 sv = *(const ulonglong2*)(stT + (qh * 8 + q8) * 4);
                sqa[q8] = sv.x; sqb[q8] = sv.y;
            }
#pragma unroll
            for (int p = 0; p < 16; p++) {
                const ulonglong2 vp2 = *(const ulonglong2*)(vtT + p * 4);
                const float4 wa0 = *(const float4*)(R0 + 16 * p + 8 * qh);
                const float4 wb0 = *(const float4*)(R0 + 16 * p + 8 * qh + 4);
                const float4 wa1 = *(const float4*)(R1 + 16 * p + 8 * qh);
                const float4 wb1 = *(const float4*)(R1 + 16 * p + 8 * qh + 4);
                u64 d0a = 0, d0b = 0, d1a = 0, d1b = 0;
                u64 wd;
                wd = dup2f(wa0.x); d0a = ffma2(wd, sqa[0], d0a); d0b = ffma2(wd, sqb[0], d0b);
                wd = dup2f(wa0.y); d0a = ffma2(wd, sqa[1], d0a); d0b = ffma2(wd, sqb[1], d0b);
                wd = dup2f(wa0.z); d0a = ffma2(wd, sqa[2], d0a); d0b = ffma2(wd, sqb[2], d0b);
                wd = dup2f(wa0.w); d0a = ffma2(wd, sqa[3], d0a); d0b = ffma2(wd, sqb[3], d0b);
                wd = dup2f(wb0.x); d0a = ffma2(wd, sqa[4], d0a); d0b = ffma2(wd, sqb[4], d0b);
                wd = dup2f(wb0.y); d0a = ffma2(wd, sqa[5], d0a); d0b = ffma2(wd, sqb[5], d0b);
                wd = dup2f(wb0.z); d0a = ffma2(wd, sqa[6], d0a); d0b = ffma2(wd, sqb[6], d0b);
                wd = dup2f(wb0.w); d0a = ffma2(wd, sqa[7], d0a); d0b = ffma2(wd, sqb[7], d0b);
                wd = dup2f(wa1.x); d1a = ffma2(wd, sqa[0], d1a); d1b = ffma2(wd, sqb[0], d1b);
                wd = dup2f(wa1.y); d1a = ffma2(wd, sqa[1], d1a); d1b = ffma2(wd, sqb[1], d1b);
                wd = dup2f(wa1.z); d1a = ffma2(wd, sqa[2], d1a); d1b = ffma2(wd, sqb[2], d1b);
                wd = dup2f(wa1.w); d1a = ffma2(wd, sqa[3], d1a); d1b = ffma2(wd, sqb[3], d1b);
                wd = dup2f(wb1.x); d1a = ffma2(wd, sqa[4], d1a); d1b = ffma2(wd, sqb[4], d1b);
                wd = dup2f(wb1.y); d1a = ffma2(wd, sqa[5], d1a); d1b = ffma2(wd, sqb[5], d1b);
                wd = dup2f(wb1.z); d1a = ffma2(wd, sqa[6], d1a); d1b = ffma2(wd, sqb[6], d1b);
                wd = dup2f(wb1.w); d1a = ffma2(wd, sqa[7], d1a); d1b = ffma2(wd, sqb[7], d1b);
                m0a = ffma2(vp2.x, d0a, m0a); m0b = ffma2(vp2.y, d0b, m0b);
                m1a = ffma2(vp2.x, d1a, m1a); m1b = ffma2(vp2.y, d1b, m1b);
            }
        }
        const float2 m001 = unpk(m0a), m023 = unpk(m0b);
        const float2 m101 = unpk(m1a), m123 = unpk(m1b);
        const float m0[4] = {m001.x, m001.y, m023.x, m023.y};
        const float m1[4] = {m101.x, m101.y, m123.x, m123.y};
#pragma unroll
        for (int pt = 0; pt < 4; pt++) {
            const float h0 = unpk(hts2[lane * 4 + pt]).x;
            const float h1 = unpk(hts2[(lane + 32) * 4 + pt]).x;
            const float th0 = fmaf(-h0, h0, 1.0f);
            const float th1 = fmaf(-h1, h1, 1.0f);
            hw[(warp * 4 + pt) * HW_STRIDE + lane] = 2.0f * th0 * m0[pt];
            hw[(warp * 4 + pt) * HW_STRIDE + lane + 32] = 2.0f * th1 * m1[pt];
        }
    }
    __syncwarp();

    // ---- u rows sub, sub+8 of own point (packed) ----
    {
        u64 u0p = 0, u1p = 0;
        const float* wc = hw + lp * HW_STRIDE;
        const float* r0 = W1r + sub * W1R_STRIDE;
        const float* r1 = W1r + (sub + 8) * W1R_STRIDE;
#pragma unroll
        for (int t = 0; t < 16; t++) {
            const ulonglong2 cc = *(const ulonglong2*)(wc + 4 * t);
            const ulonglong2 w0 = *(const ulonglong2*)(r0 + 4 * t);
            const ulonglong2 w1 = *(const ulonglong2*)(r1 + 4 * t);
            u0p = ffma2(w0.x, cc.x, u0p); u0p = ffma2(w0.y, cc.y, u0p);
            u1p = ffma2(w1.x, cc.x, u1p); u1p = ffma2(w1.y, cc.y, u1p);
        }
        const float2 f0 = unpk(u0p);
        const float2 f1 = unpk(u1p);
        usc[lp * UD_STRIDE + sub] = f0.x + f0.y;
        usc[lp * UD_STRIDE + sub + 8] = f1.x + f1.y;
    }
    __syncwarp();

    // ---- g-build (packed) + interleaved dual SPD solve ----
    const int half = lane >> 4;
    const int i16 = lane & 15;
    {
        const float* TA = tiles + half * TILE;
        const float* TB = tiles + (2 + half) * TILE;

        float growA[16], growB[16];
        {
            u64 ar2[8];
#pragma unroll
            for (int t = 0; t < 4; t++) {
                const ulonglong2 w = *(const ulonglong2*)(TA + i16 * TS + 4 * t);
                ar2[2 * t] = w.x; ar2[2 * t + 1] = w.y;
            }
#pragma unroll
            for (int jr = 0; jr < 16; jr++) {
                u64 gp = 0;
#pragma unroll
                for (int t = 0; t < 4; t++) {
                    const ulonglong2 w = *(const ulonglong2*)(TA + jr * TS + 4 * t);
                    gp = ffma2(ar2[2 * t], w.x, gp);
                    gp = ffma2(ar2[2 * t + 1], w.y, gp);
                }
                const float2 gf = unpk(gp);
                growA[jr] = gf.x + gf.y + ((jr == i16) ? 1.0f : 0.0f);
            }
#pragma unroll
            for (int t = 0; t < 4; t++) {
                const ulonglong2 w = *(const ulonglong2*)(TB + i16 * TS + 4 * t);
                ar2[2 * t] = w.x; ar2[2 * t + 1] = w.y;
            }
#pragma unroll
            for (int jr = 0; jr < 16; jr++) {
                u64 gp = 0;
#pragma unroll
                for (int t = 0; t < 4; t++) {
                    const ulonglong2 w = *(const ulonglong2*)(TB + jr * TS + 4 * t);
                    gp = ffma2(ar2[2 * t], w.x, gp);
                    gp = ffma2(ar2[2 * t + 1], w.y, gp);
                }
                const float2 gf = unpk(gp);
                growB[jr] = gf.x + gf.y + ((jr == i16) ? 1.0f : 0.0f);
            }
        }
        float rhsA = usc[(warp * 4 + half) * UD_STRIDE + i16];
        float rhsB = usc[(warp * 4 + 2 + half) * UD_STRIDE + i16];

#pragma unroll
        for (int k = 0; k < 15; k++) {
            const float pivA = __shfl_sync(FULLMASK, growA[k], k, 16);
            const float pivB = __shfl_sync(FULLMASK, growB[k], k, 16);
            const float prA = __shfl_sync(FULLMASK, rhsA, k, 16);
            const float prB = __shfl_sync(FULLMASK, rhsB, k, 16);
            const float facA = growA[k] * __fdividef(1.0f, pivA);
            const float facB = growB[k] * __fdividef(1.0f, pivB);
            const bool act = (i16 > k);
#pragma unroll
            for (int q = k + 1; q < 16; q++) {
                const float pqA = __shfl_sync(FULLMASK, growA[q], k, 16);
                const float pqB = __shfl_sync(FULLMASK, growB[q], k, 16);
                if (act) {
                    growA[q] = fmaf(-facA, pqA, growA[q]);
                    growB[q] = fmaf(-facB, pqB, growB[q]);
                }
            }
            if (act) {
                rhsA = fmaf(-facA, prA, rhsA);
                rhsB = fmaf(-facB, prB, rhsB);
            }
        }
        float dvlA = 0.0f, dvlB = 0.0f;
#pragma unroll
        for (int k = 15; k >= 0; k--) {
            const float numA = __shfl_sync(FULLMASK, rhsA, k, 16);
            const float numB = __shfl_sync(FULLMASK, rhsB, k, 16);
            const float denA = __shfl_sync(FULLMASK, growA[k], k, 16);
            const float denB = __shfl_sync(FULLMASK, growB[k], k, 16);
            const float ykA = __fdividef(numA, denA);
            const float ykB = __fdividef(numB, denB);
            if (i16 < k) {
                rhsA = fmaf(-growA[k], ykA, rhsA);
                rhsB = fmaf(-growB[k], ykB, rhsB);
            }
            if (i16 == k) { dvlA = -0.5f * ykA; dvlB = -0.5f * ykB; }
        }
        dsc[(warp * 4 + half) * UD_STRIDE + i16] = dvlA;
        dsc[(warp * 4 + 2 + half) * UD_STRIDE + i16] = dvlB;
    }
    __syncwarp();

    float2 res;
    res.x = dsc[lp * UD_STRIDE + sub];
    res.y = dsc[lp * UD_STRIDE + sub + 8];
    return res;
}

__global__ __launch_bounds__(512, 1)
void NeuralGeodesicFlows_45784351375900_kernel(
    const float* __restrict__ z_in,
    const float* __restrict__ t_ptr,
    const float* __restrict__ W1,
    const float* __restrict__ b1,
    const float* __restrict__ W2,
    const float* __restrict__ b2,
    const int* __restrict__ ns_ptr,
    float* __restrict__ z_out,
    int B)
{
    extern __shared__ float smem[];
    const int tid = threadIdx.x;

    for (int idx = tid; idx < 64 * 256; idx += 512)
        smem[W2S_OFF + (idx >> 8) * W2_STRIDE + (idx & 255)] = W2[idx];
    for (int idx = tid; idx < 16 * 64; idx += 512) {
        const int a = idx >> 6, c = idx & 63;
        const float w = W1[idx];
        smem[W1R_OFF + a * W1R_STRIDE + c] = w;
        smem[W1T_OFF + c * W1T_STRIDE + a] = w;
    }
    if (tid < 64) smem[B1S_OFF + tid] = b1[tid];
    if (tid < 256) smem[B2S_OFF + tid] = b2[tid];
    __syncthreads();

    const int warp = tid >> 5;
    const int lane = tid & 31;
    const int sub = lane & 7;
    const int g = lane >> 3;
    const int point = blockIdx.x * 64 + warp * 4 + g;
    if (point >= B) return;

    const float* zp = z_in + point * 32;
    float xs0 = zp[sub];
    float xs1 = zp[sub + 8];
    float vs0 = zp[16 + sub];
    float vs1 = zp[24 + sub];

    const float t = *t_ptr;
    const int ns = *ns_ptr;
    const float dt = t / (float)ns;
    const float hdt = 0.5f * dt;
    const float dt6 = dt * (1.0f / 6.0f);

    for (int s = 0; s < ns; s++) {
        const float2 a1 = geo_dv(xs0, xs1, vs0, vs1, lane, sub, g, warp);
        const float v20 = fmaf(hdt, a1.x, vs0);
        const float v21 = fmaf(hdt, a1.y, vs1);
        const float2 a2 = geo_dv(fmaf(hdt, vs0, xs0), fmaf(hdt, vs1, xs1),
                                 v20, v21, lane, sub, g, warp);
        const float v30 = fmaf(hdt, a2.x, vs0);
        const float v31 = fmaf(hdt, a2.y, vs1);
        const float2 a3 = geo_dv(fmaf(hdt, v20, xs0), fmaf(hdt, v21, xs1),
                                 v30, v31, lane, sub, g, warp);
        const float v40 = fmaf(dt, a3.x, vs0);
        const float v41 = fmaf(dt, a3.y, vs1);
        const float2 a4 = geo_dv(fmaf(dt, v30, xs0), fmaf(dt, v31, xs1),
                                 v40, v41, lane, sub, g, warp);
        xs0 = fmaf(dt6, vs0 + 2.0f * v20 + 2.0f * v30 + v40, xs0);
        xs1 = fmaf(dt6, vs1 + 2.0f * v21 + 2.0f * v31 + v41, xs1);
        vs0 = fmaf(dt6, a1.x + 2.0f * a2.x + 2.0f * a3.x + a4.x, vs0);
        vs1 = fmaf(dt6, a1.y + 2.0f * a2.y + 2.0f * a3.y + a4.y, vs1);
    }

    float* op = z_out + point * 32;
    op[sub] = xs0;
    op[sub + 8] = xs1;
    op[16 + sub] = vs0;
    op[24 + sub] = vs1;
}

extern "C" void kernel_launch(void* const* d_in, const int* in_sizes, int n_in,
                              void* d_out, int out_size)
{
    const float* z  = (const float*)d_in[0];
    const float* t  = (const float*)d_in[1];
    const float* W1 = (const float*)d_in[2];
    const float* b1 = (const float*)d_in[3];
    const float* W2 = (const float*)d_in[4];
    const float* b2 = (const float*)d_in[5];
    const int*   ns = (const int*)d_in[6];
    float* out = (float*)d_out;

    const int B = in_sizes[0] / 32;
    const int grid = (B + 63) / 64;

    cudaFuncSetAttribute(NeuralGeodesicFlows_45784351375900_kernel,
                         cudaFuncAttributeMaxDynamicSharedMemorySize, SMEM_BYTES);
    NeuralGeodesicFlows_45784351375900_kernel<<<grid, 512, SMEM_BYTES>>>(
        z, t, W1, b1, W2, b2, ns, out, B);
}